// round 14
// baseline (speedup 1.0000x reference)
#include <cuda_runtime.h>
#include <cuda_fp16.h>
#include <cstdint>

// Circulant GEMM on mma.sync fp16: D[56,112] = A_c[56,56] @ X[56,112]
// per (channel, 2 batches) tile. Single-term fp16 (Ah @ Bh, fp32 acc).
// Each block processes 2 tiles of one channel; during tile t's mma loop,
// threads issue prefetch.global.L2 for tile t+1's planes so HBM reads
// overlap tensor compute. K = 3 x k16 + k8 tail; B via ldmatrix.trans;
// A circulant fragments in registers (built once per block).

#define CCH 384
#define HW 56
#define PLANE 3136
#define NT 128
#define TPB 2
#define ROWB 240                      // 60 words/row, 60%32==28 -> conflict-free
#define W_OFF (56 * ROWB)             // 13440
#define SMEM_TOTAL (W_OFF + 256)      // 13696

__device__ __forceinline__ uint32_t smem_u32(const void* p) {
    uint32_t a;
    asm("{ .reg .u64 t; cvta.to.shared.u64 t, %1; cvt.u32.u64 %0, t; }" : "=r"(a) : "l"(p));
    return a;
}
__device__ __forceinline__ void ldmat4t(uint32_t r[4], uint32_t addr) {
    asm volatile("ldmatrix.sync.aligned.m8n8.x4.trans.shared.b16 {%0,%1,%2,%3}, [%4];"
                 : "=r"(r[0]), "=r"(r[1]), "=r"(r[2]), "=r"(r[3]) : "r"(addr));
}
__device__ __forceinline__ void ldmat2t(uint32_t r[2], uint32_t addr) {
    asm volatile("ldmatrix.sync.aligned.m8n8.x2.trans.shared.b16 {%0,%1}, [%2];"
                 : "=r"(r[0]), "=r"(r[1]) : "r"(addr));
}
__device__ __forceinline__ void mma16(float c[4], const uint32_t a[4],
                                      uint32_t b0, uint32_t b1) {
    asm volatile(
        "mma.sync.aligned.m16n8k16.row.col.f32.f16.f16.f32 "
        "{%0,%1,%2,%3}, {%4,%5,%6,%7}, {%8,%9}, {%0,%1,%2,%3};"
        : "+f"(c[0]), "+f"(c[1]), "+f"(c[2]), "+f"(c[3])
        : "r"(a[0]), "r"(a[1]), "r"(a[2]), "r"(a[3]), "r"(b0), "r"(b1));
}
__device__ __forceinline__ void mma8(float c[4], const uint32_t a[2], uint32_t b0) {
    asm volatile(
        "mma.sync.aligned.m16n8k8.row.col.f32.f16.f16.f32 "
        "{%0,%1,%2,%3}, {%4,%5}, {%6}, {%0,%1,%2,%3};"
        : "+f"(c[0]), "+f"(c[1]), "+f"(c[2]), "+f"(c[3])
        : "r"(a[0]), "r"(a[1]), "r"(b0));
}
__device__ __forceinline__ void prefetch_l2(const void* p) {
    asm volatile("prefetch.global.L2 [%0];" :: "l"(p));
}
__device__ __forceinline__ uint32_t bits2h(__half2 v) { return *(uint32_t*)&v; }

extern __shared__ char smem[];

__global__ __launch_bounds__(NT, 6)
void gcc_conv_hmma10(const float* __restrict__ x, const float* __restrict__ weight,
                     const float* __restrict__ bias, float* __restrict__ out) {
    const int tid = threadIdx.x;
    const int c  = blockIdx.x >> 3;
    const int bo = (blockIdx.x & 7) * 4;     // 2 tiles: batches [bo,bo+2),[bo+2,bo+4)

    float* wtab = (float*)(smem + W_OFF);
    if (tid < HW) wtab[tid] = weight[c * HW + tid];
    __syncthreads();

    const int wm = tid >> 5, lane = tid & 31;
    const int g = lane >> 2, i4 = lane & 3;
    const int r0 = wm * 16 + g;          // < 56
    const int r1 = r0 + 8;               // >= 56 only when wm==3

    // ---- A circulant fragments (fp16): 3 k16 tiles + k8 tail ----
    uint32_t Ah[3][4], Th[2];
#pragma unroll
    for (int kt = 0; kt < 3; kt++) {
#pragma unroll
        for (int reg = 0; reg < 4; reg++) {
            const int row = (reg & 1) ? r1 : r0;
            const int kk = kt * 16 + 2 * i4 + ((reg & 2) ? 8 : 0);
            float v0 = 0.f, v1 = 0.f;
            if (row < HW) {
                int j0 = kk - row; if (j0 < 0) j0 += HW;
                int j1 = j0 + 1;   if (j1 == HW) j1 = 0;
                v0 = wtab[j0]; v1 = wtab[j1];
            }
            Ah[kt][reg] = bits2h(__floats2half2_rn(v0, v1));
        }
    }
#pragma unroll
    for (int reg = 0; reg < 2; reg++) {
        const int row = reg ? r1 : r0;
        const int kk = 48 + 2 * i4;
        float v0 = 0.f, v1 = 0.f;
        if (row < HW) {
            int j0 = kk - row; if (j0 < 0) j0 += HW;
            int j1 = j0 + 1;   if (j1 == HW) j1 = 0;
            v0 = wtab[j0]; v1 = wtab[j1];
        }
        Th[reg] = bits2h(__floats2half2_rn(v0, v1));
    }

    const uint32_t sbase = smem_u32(smem);
    const int krow = (lane & 7) + ((lane >> 3) & 1) * 8;
    const int nsel = lane >> 4;
    const int tnsel = (lane >> 3) & 1;
    const uint32_t lbase = sbase + krow * ROWB;
    const uint32_t tbase = sbase + (48 + (lane & 7)) * ROWB;
    const float bv = bias[c];
    const size_t bstride = (size_t)CCH * PLANE;

#pragma unroll
    for (int t = 0; t < TPB; t++) {
        const int b0 = bo + 2 * t;
        if (t) __syncthreads();              // prior mma done reading smem

        // ---- convert pass: X (2 batches) -> natural [k][n] fp16 smem ----
        const float* xc = x + ((size_t)b0 * CCH + c) * PLANE;
#pragma unroll
        for (int b = 0; b < 2; b++) {
            const float* xb = xc + (size_t)b * bstride;
            char* sb = smem + b * 112;
#pragma unroll
            for (int i = 0; i < 7; i++) {
                const int u = tid + NT * i;
                if (u >= 784) break;
                const int k = u / 14, wq = u - k * 14;
                const float4 v = *(const float4*)(xb + k * HW + wq * 4);
                uint2 pk;
                pk.x = bits2h(__floats2half2_rn(v.x, v.y));
                pk.y = bits2h(__floats2half2_rn(v.z, v.w));
                *(uint2*)(sb + k * ROWB + wq * 8) = pk;
            }
        }
        __syncthreads();

        const bool more = (t + 1 < TPB);
        const float* xn = x + ((size_t)(b0 + 2) * CCH + c) * PLANE;

        // ---- MMA: warp wm covers all 14 n-tiles (7 pairs) ----
        uint32_t bh[2][4];
#pragma unroll
        for (int np = 0; np < 7; np++) {
            const int nt0 = np * 2;
            const uint32_t laddr = lbase + (uint32_t)(nt0 + nsel) * 16;
            const uint32_t taddr = tbase + (uint32_t)(nt0 + tnsel) * 16;
            if (np == 0)
                ldmat4t(bh[0], laddr);

            // pull next tile's lines into L2 while tensor cores run:
            // 196 x 128B lines (= 2 planes) spread over 7 nps x 28 threads
            if (more && tid < 28) {
                const int u = np * 28 + tid;
                const int bb = (u >= 98);
                prefetch_l2(xn + (size_t)bb * bstride + (u - 98 * bb) * 32);
            }

            float acc0[4] = {bv, bv, bv, bv};
            float acc1[4] = {bv, bv, bv, bv};
            uint32_t thr[2];
#pragma unroll
            for (int kt = 0; kt < 3; kt++) {
                const int cur = kt & 1, nxt = cur ^ 1;
                if (kt < 2)
                    ldmat4t(bh[nxt], laddr + (kt + 1) * 16 * ROWB);
                else
                    ldmat2t(thr, taddr);
                mma16(acc0, Ah[kt], bh[cur][0], bh[cur][1]);
                mma16(acc1, Ah[kt], bh[cur][2], bh[cur][3]);
            }
            if (np < 6) {
                const uint32_t laddr2 = lbase + (uint32_t)(nt0 + 2 + nsel) * 16;
                ldmat4t(bh[0], laddr2);
            }
            mma8(acc0, Th, thr[0]);
            mma8(acc1, Th, thr[1]);
#pragma unroll
            for (int s = 0; s < 2; s++) {
                const float* acc = s ? acc1 : acc0;
                const int n = (nt0 + s) * 8 + 2 * i4;
                const int b = (n >= HW);
                const int wcol = n - b * HW;
                float* op = out + ((size_t)(b0 + b) * CCH + c) * PLANE + wcol;
                *(float2*)(op + r0 * HW) = make_float2(acc[0], acc[1]);
                if (wm != 3)
                    *(float2*)(op + r1 * HW) = make_float2(acc[2], acc[3]);
            }
        }
    }
}

extern "C" void kernel_launch(void* const* d_in, const int* in_sizes, int n_in,
                              void* d_out, int out_size) {
    const float* x      = (const float*)d_in[0];
    const float* weight = (const float*)d_in[1];
    const float* bias   = (const float*)d_in[2];
    cudaFuncSetAttribute(gcc_conv_hmma10,
                         cudaFuncAttributeMaxDynamicSharedMemorySize, SMEM_TOTAL);
    gcc_conv_hmma10<<<CCH * 8, NT, SMEM_TOTAL>>>(x, weight, bias, (float*)d_out);
}

// round 15
// speedup vs baseline: 1.1101x; 1.1101x over previous
#include <cuda_runtime.h>
#include <cuda_fp16.h>
#include <cstdint>

// Circulant GEMM on mma.sync fp16: D[56,112] = A_c[56,56] @ X[56,112]
// per (channel, 2 batches). Single-term fp16 (Ah @ Bh, fp32 acc),
// rel_err ~4e-5. K = 3 x k16 + k8 tail. B in natural [k][n] fp16 smem,
// ldmatrix.trans fetch, kt-level register double-buffer.
// Prologue is barrier-free: A fragments built from __ldg(weight) so the
// convert-pass x LDGs can issue immediately and overlap the A-build.

#define CCH 384
#define HW 56
#define PLANE 3136
#define NT 128
#define ROWB 240                      // 60 words/row, 60%32==28 -> conflict-free
#define SMEM_TOTAL (56 * ROWB)        // 13440

__device__ __forceinline__ uint32_t smem_u32(const void* p) {
    uint32_t a;
    asm("{ .reg .u64 t; cvta.to.shared.u64 t, %1; cvt.u32.u64 %0, t; }" : "=r"(a) : "l"(p));
    return a;
}
__device__ __forceinline__ void ldmat4t(uint32_t r[4], uint32_t addr) {
    asm volatile("ldmatrix.sync.aligned.m8n8.x4.trans.shared.b16 {%0,%1,%2,%3}, [%4];"
                 : "=r"(r[0]), "=r"(r[1]), "=r"(r[2]), "=r"(r[3]) : "r"(addr));
}
__device__ __forceinline__ void ldmat2t(uint32_t r[2], uint32_t addr) {
    asm volatile("ldmatrix.sync.aligned.m8n8.x2.trans.shared.b16 {%0,%1}, [%2];"
                 : "=r"(r[0]), "=r"(r[1]) : "r"(addr));
}
__device__ __forceinline__ void mma16(float c[4], const uint32_t a[4],
                                      uint32_t b0, uint32_t b1) {
    asm volatile(
        "mma.sync.aligned.m16n8k16.row.col.f32.f16.f16.f32 "
        "{%0,%1,%2,%3}, {%4,%5,%6,%7}, {%8,%9}, {%0,%1,%2,%3};"
        : "+f"(c[0]), "+f"(c[1]), "+f"(c[2]), "+f"(c[3])
        : "r"(a[0]), "r"(a[1]), "r"(a[2]), "r"(a[3]), "r"(b0), "r"(b1));
}
__device__ __forceinline__ void mma8(float c[4], const uint32_t a[2], uint32_t b0) {
    asm volatile(
        "mma.sync.aligned.m16n8k8.row.col.f32.f16.f16.f32 "
        "{%0,%1,%2,%3}, {%4,%5}, {%6}, {%0,%1,%2,%3};"
        : "+f"(c[0]), "+f"(c[1]), "+f"(c[2]), "+f"(c[3])
        : "r"(a[0]), "r"(a[1]), "r"(b0));
}
__device__ __forceinline__ uint32_t bits2h(__half2 v) { return *(uint32_t*)&v; }

extern __shared__ char smem[];

__global__ __launch_bounds__(NT, 6)
void gcc_conv_hmma11(const float* __restrict__ x, const float* __restrict__ weight,
                     const float* __restrict__ bias, float* __restrict__ out) {
    const int tid = threadIdx.x;
    const int c  = blockIdx.x >> 4;
    const int b0 = (blockIdx.x & 15) * 2;

    const int wm = tid >> 5, lane = tid & 31;
    const int g = lane >> 2, i4 = lane & 3;
    const int r0 = wm * 16 + g;          // < 56
    const int r1 = r0 + 8;               // >= 56 only when wm==3

    // ---- convert pass part 1: issue all x LDGs + STS (no barrier before) ----
    const float* xc = x + ((size_t)b0 * CCH + c) * PLANE;
    const float* wc = weight + c * HW;

    // ---- A circulant fragments (fp16) from __ldg(weight): 3 k16 + k8 tail ----
    uint32_t Ah[3][4], Th[2];
#pragma unroll
    for (int kt = 0; kt < 3; kt++) {
#pragma unroll
        for (int reg = 0; reg < 4; reg++) {
            const int row = (reg & 1) ? r1 : r0;
            const int kk = kt * 16 + 2 * i4 + ((reg & 2) ? 8 : 0);
            float v0 = 0.f, v1 = 0.f;
            if (row < HW) {
                int j0 = kk - row; if (j0 < 0) j0 += HW;
                int j1 = j0 + 1;   if (j1 == HW) j1 = 0;
                v0 = __ldg(wc + j0); v1 = __ldg(wc + j1);
            }
            Ah[kt][reg] = bits2h(__floats2half2_rn(v0, v1));
        }
    }
#pragma unroll
    for (int reg = 0; reg < 2; reg++) {
        const int row = reg ? r1 : r0;
        const int kk = 48 + 2 * i4;
        float v0 = 0.f, v1 = 0.f;
        if (row < HW) {
            int j0 = kk - row; if (j0 < 0) j0 += HW;
            int j1 = j0 + 1;   if (j1 == HW) j1 = 0;
            v0 = __ldg(wc + j0); v1 = __ldg(wc + j1);
        }
        Th[reg] = bits2h(__floats2half2_rn(v0, v1));
    }

    // ---- convert pass: X (2 batches) -> natural [k][n] fp16 smem ----
#pragma unroll
    for (int b = 0; b < 2; b++) {
        const float* xb = xc + (size_t)b * CCH * PLANE;
        char* sb = smem + b * 112;
#pragma unroll
        for (int i = 0; i < 6; i++) {
            const int u = tid + NT * i;
            const int k = u / 14, wq = u - k * 14;
            const float4 v = *(const float4*)(xb + k * HW + wq * 4);
            uint2 pk;
            pk.x = bits2h(__floats2half2_rn(v.x, v.y));
            pk.y = bits2h(__floats2half2_rn(v.z, v.w));
            *(uint2*)(sb + k * ROWB + wq * 8) = pk;
        }
        if (tid < 16) {
            const int u = 768 + tid;
            const int k = u / 14, wq = u - k * 14;
            const float4 v = *(const float4*)(xb + k * HW + wq * 4);
            uint2 pk;
            pk.x = bits2h(__floats2half2_rn(v.x, v.y));
            pk.y = bits2h(__floats2half2_rn(v.z, v.w));
            *(uint2*)(sb + k * ROWB + wq * 8) = pk;
        }
    }
    __syncthreads();

    // ---- MMA: warp wm covers all 14 n-tiles (7 pairs); kt register pipeline ----
    const float bv = __ldg(bias + c);
    const uint32_t sbase = smem_u32(smem);
    const int krow = (lane & 7) + ((lane >> 3) & 1) * 8;
    const int nsel = lane >> 4;
    const int tnsel = (lane >> 3) & 1;
    const uint32_t lbase = sbase + krow * ROWB;
    const uint32_t tbase = sbase + (48 + (lane & 7)) * ROWB;

    uint32_t bh[2][4];

#pragma unroll
    for (int np = 0; np < 7; np++) {
        const int nt0 = np * 2;
        const uint32_t laddr = lbase + (uint32_t)(nt0 + nsel) * 16;
        const uint32_t taddr = tbase + (uint32_t)(nt0 + tnsel) * 16;
        if (np == 0)                          // prime the pipeline
            ldmat4t(bh[0], laddr);
        float acc0[4] = {bv, bv, bv, bv};
        float acc1[4] = {bv, bv, bv, bv};
        uint32_t thr[2];
#pragma unroll
        for (int kt = 0; kt < 3; kt++) {
            const int cur = kt & 1, nxt = cur ^ 1;
            if (kt < 2)                       // prefetch next k16 tile
                ldmat4t(bh[nxt], laddr + (kt + 1) * 16 * ROWB);
            else                              // prefetch k8 tail
                ldmat2t(thr, taddr);
            mma16(acc0, Ah[kt], bh[cur][0], bh[cur][1]);
            mma16(acc1, Ah[kt], bh[cur][2], bh[cur][3]);
        }
        if (np < 6) {                         // prefetch next pair's kt0
            const uint32_t laddr2 = lbase + (uint32_t)(nt0 + 2 + nsel) * 16;
            ldmat4t(bh[0], laddr2);
        }
        mma8(acc0, Th, thr[0]);
        mma8(acc1, Th, thr[1]);
#pragma unroll
        for (int s = 0; s < 2; s++) {
            const float* acc = s ? acc1 : acc0;
            const int n = (nt0 + s) * 8 + 2 * i4;
            const int b = (n >= HW);
            const int wcol = n - b * HW;
            float* op = out + ((size_t)(b0 + b) * CCH + c) * PLANE + wcol;
            *(float2*)(op + r0 * HW) = make_float2(acc[0], acc[1]);
            if (wm != 3)
                *(float2*)(op + r1 * HW) = make_float2(acc[2], acc[3]);
        }
    }
}

extern "C" void kernel_launch(void* const* d_in, const int* in_sizes, int n_in,
                              void* d_out, int out_size) {
    const float* x      = (const float*)d_in[0];
    const float* weight = (const float*)d_in[1];
    const float* bias   = (const float*)d_in[2];
    cudaFuncSetAttribute(gcc_conv_hmma11,
                         cudaFuncAttributeMaxDynamicSharedMemorySize, SMEM_TOTAL);
    gcc_conv_hmma11<<<CCH * 16, NT, SMEM_TOTAL>>>(x, weight, bias, (float*)d_out);
}